// round 3
// baseline (speedup 1.0000x reference)
#include <cuda_runtime.h>
#include <cstdint>

// x:   [B=8192, F=32, E=64] f32
// W:   [E=64, E=64] f32
// out: [B, P=496, E=64] f32,  out[b,p,:] = (x[b,i_p,:] @ W) * x[b,j_p,:]
// (i_p, j_p) = triu_indices(32, k=1), row-major pair order.

#define BB 8192
#define FF 32
#define EE 64
#define PP 496            // FF*(FF-1)/2
#define NV4 (PP * (EE/4)) // 7936 float4 outputs per batch row
#define NTHREADS 256

__global__ __launch_bounds__(NTHREADS)
void bilinear_kernel(const float* __restrict__ x,
                     const float* __restrict__ W,
                     float* __restrict__ out)
{
    __shared__ float xs[FF * EE];        // 8 KB  : x[b]
    __shared__ float ws[EE * EE];        // 16 KB : W
    __shared__ float xw[FF * EE];        // 8 KB  : x[b] @ W
    __shared__ unsigned short pairs[PP]; // (i<<8)|j

    const int tid = threadIdx.x;
    const int b   = blockIdx.x;

    // ---- load x[b] (512 float4) and W (1024 float4) into SMEM ----
    {
        const float4* xg = reinterpret_cast<const float4*>(x) + (size_t)b * (FF * EE / 4);
        float4* xs4 = reinterpret_cast<float4*>(xs);
        #pragma unroll
        for (int q = tid; q < FF * EE / 4; q += NTHREADS)
            xs4[q] = xg[q];

        const float4* wg = reinterpret_cast<const float4*>(W);
        float4* ws4 = reinterpret_cast<float4*>(ws);
        #pragma unroll
        for (int q = tid; q < EE * EE / 4; q += NTHREADS)
            ws4[q] = wg[q];
    }

    // ---- build pair table: p -> (i, j), triu row-major order ----
    // Terminates: for p<=495, len walks 31 down to at most 1 with rem shrinking.
    for (int p = tid; p < PP; p += NTHREADS) {
        int i = 0, rem = p, len = FF - 1;
        while (rem >= len) { rem -= len; --len; ++i; }
        pairs[p] = (unsigned short)((i << 8) | (i + 1 + rem));
    }

    __syncthreads();

    // ---- matmul: xw[f][e] = sum_k xs[f][k] * W[k][e] ----
    // 256 threads: 2 f-rows x 4 e-cols each.
    {
        const int e0 = (tid & 15) * 4;
        const int f0 = (tid >> 4) * 2;

        float4 a0 = make_float4(0.f, 0.f, 0.f, 0.f);
        float4 a1 = make_float4(0.f, 0.f, 0.f, 0.f);

        #pragma unroll 8
        for (int k = 0; k < EE; ++k) {
            const float4 w = *reinterpret_cast<const float4*>(&ws[k * EE + e0]);
            const float xa = xs[ f0      * EE + k];
            const float xb = xs[(f0 + 1) * EE + k];
            a0.x += xa * w.x; a0.y += xa * w.y; a0.z += xa * w.z; a0.w += xa * w.w;
            a1.x += xb * w.x; a1.y += xb * w.y; a1.z += xb * w.z; a1.w += xb * w.w;
        }
        *reinterpret_cast<float4*>(&xw[ f0      * EE + e0]) = a0;
        *reinterpret_cast<float4*>(&xw[(f0 + 1) * EE + e0]) = a1;
    }

    __syncthreads();

    // ---- store phase: out[b,p,e] = xw[i_p][e] * xs[j_p][e] ----
    // Each thread owns a fixed float4-lane v = tid & 15 across 31 pairs
    // (q = p*16 + v, p = tid>>4 + 16*iter). Fully coalesced 128B stores.
    {
        const float4* xw4 = reinterpret_cast<const float4*>(xw);
        const float4* xs4 = reinterpret_cast<const float4*>(xs);
        float4* og = reinterpret_cast<float4*>(out) + (size_t)b * NV4;

        #pragma unroll 4
        for (int q = tid; q < NV4; q += NTHREADS) {
            const int p  = q >> 4;      // pair index 0..495
            const int v  = q & 15;      // float4 lane within E
            const int pr = pairs[p];
            const int i  = pr >> 8;
            const int j  = pr & 255;
            const float4 a = xw4[i * (EE / 4) + v];
            const float4 c = xs4[j * (EE / 4) + v];
            float4 r;
            r.x = a.x * c.x; r.y = a.y * c.y; r.z = a.z * c.z; r.w = a.w * c.w;
            __stcs(&og[q], r);          // write-once output: streaming store
        }
    }
}

extern "C" void kernel_launch(void* const* d_in, const int* in_sizes, int n_in,
                              void* d_out, int out_size)
{
    const float* x = (const float*)d_in[0]; // [8192, 32, 64]
    const float* W = (const float*)d_in[1]; // [64, 64]
    float* out = (float*)d_out;             // [8192, 496, 64]
    (void)in_sizes; (void)n_in; (void)out_size;

    bilinear_kernel<<<BB, NTHREADS>>>(x, W, out);
}

// round 4
// speedup vs baseline: 1.1547x; 1.1547x over previous
#include <cuda_runtime.h>
#include <cstdint>

// x:   [B=8192, F=32, E=64] f32
// W:   [E=64, E=64] f32
// out: [B, P=496, E=64] f32,  out[b,p,:] = (x[b,i_p,:] @ W) * x[b,j_p,:]
// (i_p, j_p) = triu_indices(32, k=1), row-major pair order.

#define BB 8192
#define FF 32
#define EE 64
#define PP 496
#define NV4 (PP * (EE/4)) // 7936 float4 per batch row
#define NTHREADS 256

// pairs before row i: sum_{t<i} (31-t) = 31*i - i*(i-1)/2
__device__ __forceinline__ int rowstart(int i) {
    return 31 * i - (i * (i - 1)) / 2;
}

__global__ __launch_bounds__(NTHREADS)
void bilinear_kernel(const float* __restrict__ x,
                     const float* __restrict__ W,
                     float* __restrict__ out)
{
    __shared__ float xs[FF * EE];  // 8 KB  : x[b]
    __shared__ float ws[EE * EE];  // 16 KB : W
    __shared__ float xw[FF * EE];  // 8 KB  : x[b] @ W

    const int tid = threadIdx.x;
    const int b   = blockIdx.x;

    // ---- load x[b] (512 float4) and W (1024 float4) into SMEM ----
    {
        const float4* xg = reinterpret_cast<const float4*>(x) + (size_t)b * (FF * EE / 4);
        float4* xs4 = reinterpret_cast<float4*>(xs);
        #pragma unroll
        for (int q = tid; q < FF * EE / 4; q += NTHREADS)
            xs4[q] = xg[q];

        const float4* wg = reinterpret_cast<const float4*>(W);
        float4* ws4 = reinterpret_cast<float4*>(ws);
        #pragma unroll
        for (int q = tid; q < EE * EE / 4; q += NTHREADS)
            ws4[q] = wg[q];
    }

    __syncthreads();

    // ---- matmul: xw[f][e] = sum_k xs[f][k] * W[k][e] ----
    // 256 threads: 2 f-rows x 4 e-cols each.
    {
        const int e0 = (tid & 15) * 4;
        const int f0 = (tid >> 4) * 2;

        float4 a0 = make_float4(0.f, 0.f, 0.f, 0.f);
        float4 a1 = make_float4(0.f, 0.f, 0.f, 0.f);

        #pragma unroll 8
        for (int k = 0; k < EE; ++k) {
            const float4 w = *reinterpret_cast<const float4*>(&ws[k * EE + e0]);
            const float xa = xs[ f0      * EE + k];
            const float xb = xs[(f0 + 1) * EE + k];
            a0.x += xa * w.x; a0.y += xa * w.y; a0.z += xa * w.z; a0.w += xa * w.w;
            a1.x += xb * w.x; a1.y += xb * w.y; a1.z += xb * w.z; a1.w += xb * w.w;
        }
        *reinterpret_cast<float4*>(&xw[ f0      * EE + e0]) = a0;
        *reinterpret_cast<float4*>(&xw[(f0 + 1) * EE + e0]) = a1;
    }

    __syncthreads();

    // ---- store phase: out[b,p,e] = xw[i_p][e] * xs[j_p][e] ----
    // 16 groups of 16 lanes. Group g owns row i=g (31-g pairs) then row
    // i=30-g (g+1 pairs); group 15 owns only i=15 (16 pairs). 32 rows per
    // group (balanced). xw[i][v] cached in registers -> inner body is
    // exactly 1 LDS.128 + 1 STG.128 per output float4.
    {
        const int v = tid & 15;   // float4 lane within E
        const int g = tid >> 4;   // group id 0..15

        const float4* xw4 = reinterpret_cast<const float4*>(xw);
        const float4* xs4 = reinterpret_cast<const float4*>(xs);
        float4* og = reinterpret_cast<float4*>(out) + (size_t)b * NV4;

        // first row: i = g
        {
            const int i = g;
            const float4 a = xw4[i * 16 + v];
            float4* o = og + (size_t)rowstart(i) * 16 + v;
            #pragma unroll 4
            for (int j = i + 1; j < FF; ++j, o += 16) {
                const float4 c = xs4[j * 16 + v];
                float4 r;
                r.x = a.x * c.x; r.y = a.y * c.y; r.z = a.z * c.z; r.w = a.w * c.w;
                __stcs(o, r);
            }
        }

        // second row: i = 30 - g (skip for g == 15: would repeat i = 15)
        if (g < 15) {
            const int i = 30 - g;
            const float4 a = xw4[i * 16 + v];
            float4* o = og + (size_t)rowstart(i) * 16 + v;
            #pragma unroll 4
            for (int j = i + 1; j < FF; ++j, o += 16) {
                const float4 c = xs4[j * 16 + v];
                float4 r;
                r.x = a.x * c.x; r.y = a.y * c.y; r.z = a.z * c.z; r.w = a.w * c.w;
                __stcs(o, r);
            }
        }
    }
}

extern "C" void kernel_launch(void* const* d_in, const int* in_sizes, int n_in,
                              void* d_out, int out_size)
{
    const float* x = (const float*)d_in[0]; // [8192, 32, 64]
    const float* W = (const float*)d_in[1]; // [64, 64]
    float* out = (float*)d_out;             // [8192, 496, 64]
    (void)in_sizes; (void)n_in; (void)out_size;

    bilinear_kernel<<<BB, NTHREADS>>>(x, W, out);
}